// round 5
// baseline (speedup 1.0000x reference)
#include <cuda_runtime.h>
#include <math.h>

// Problem constants
#define TOKENS   65536          // 64 * 32 * 32
#define DDIM     256
#define KCODES   4096
#define HW       1024           // 32*32
#define BM       128            // tokens per CTA
#define BN       128            // codes per tile
#define BK       32             // D-chunk per inner tile
#define APAD     132            // padded leading dim for smem tiles
#define NB1      (TOKENS / BM)  // 512 CTAs
#define OUT_ELEMS 16777216      // 64*256*32*32

// Packed fp32x2 FMA (Blackwell FFMA2) — exact fp32 per component, 2x FFMA rate.
#define FMA_F32X2(d, a, b, c) \
    asm("fma.rn.f32x2 %0, %1, %2, %3;" : "=l"(d) : "l"(a), "l"(b), "l"(c))
#define PACK2(out, xu, yu) \
    asm("mov.b64 %0, {%1, %2};" : "=l"(out) : "r"(xu), "r"(yu))
#define UNPACK2(lo, hi, in) \
    asm("mov.b64 {%0, %1}, %2;" : "=r"(lo), "=r"(hi) : "l"(in))

// Scratch (no allocation allowed -> device globals)
__device__ float g_enorm2[KCODES];
__device__ int   g_idx[TOKENS];
__device__ float g_partial[NB1];
__device__ int   g_counts[KCODES];

// ---------------------------------------------------------------------------
// Kernel 0: per-code squared norms + zero histogram
// ---------------------------------------------------------------------------
__global__ void k_prep(const float* __restrict__ emb) {
    int row = blockIdx.x;
    float v = emb[(size_t)row * DDIM + threadIdx.x];
    float s = v * v;
    __shared__ float red[8];
    #pragma unroll
    for (int o = 16; o > 0; o >>= 1) s += __shfl_down_sync(0xffffffffu, s, o);
    if ((threadIdx.x & 31) == 0) red[threadIdx.x >> 5] = s;
    __syncthreads();
    if (threadIdx.x == 0) {
        float t = 0.f;
        #pragma unroll
        for (int i = 0; i < 8; i++) t += red[i];
        g_enorm2[row] = t;
        g_counts[row] = 0;
    }
}

// ---------------------------------------------------------------------------
// Kernel 1: fused distance GEMM (packed FFMA2) + quantized argmin
//   d(n,k) = fl( fl(xn2_n + en2_k) - 2 * dot(n,k) )   [reference-exact chain]
//   argmin ties broken by LOWEST code index (packed u64 compare).
// ---------------------------------------------------------------------------
__global__ void __launch_bounds__(256, 1)
k_argmin(const float* __restrict__ x, const float* __restrict__ emb) {
    extern __shared__ float sm[];
    float* As = sm;                        // DDIM * APAD floats (A[d][m])
    float* Bs = sm + DDIM * APAD;          // BK * APAD floats   (B[k][n])
    float* sen = Bs + BK * APAD;           // KCODES floats (|e_k|^2)
    __shared__ float sxn2[BM];

    const int t    = threadIdx.x;
    const int base = blockIdx.x * BM;
    const int b    = base >> 10;
    const int hw0  = base & 1023;
    const float* xb = x + (size_t)b * (DDIM * HW) + hw0;

    // ---- stage |e|^2 table into shared ----
    #pragma unroll
    for (int i = 0; i < KCODES / 256; i++)
        sen[i * 256 + t] = g_enorm2[i * 256 + t];

    // ---- Load A: As[d*APAD + m] = x[b, d, hw0+m], coalesced float4 over m ----
    {
        const int lane4 = (t & 31) * 4;
        const int d0    = t >> 5;
        #pragma unroll
        for (int dd = 0; dd < DDIM; dd += 8) {
            int d = dd + d0;
            float4 v = *(const float4*)(xb + (size_t)d * HW + lane4);
            *(float4*)(&As[d * APAD + lane4]) = v;
        }
    }
    __syncthreads();

    // ---- per-token |x_n|^2 (fp32) ----
    if (t < BM) {
        float s = 0.f;
        #pragma unroll 8
        for (int d = 0; d < DDIM; d++) {
            float v = As[d * APAD + t];
            s = fmaf(v, v, s);
        }
        sxn2[t] = s;
    }
    __syncthreads();

    const int ty = t >> 4;   // token group 0..15 (rows ty*8 .. ty*8+7)
    const int tx = t & 15;   // code  group 0..15 (cols tx*8 .. tx*8+7)

    float myxn2[8];
    #pragma unroll
    for (int i = 0; i < 8; i++) myxn2[i] = sxn2[ty * 8 + i];

    float best[8];
    int   bidx[8];
    #pragma unroll
    for (int i = 0; i < 8; i++) { best[i] = 3.4e38f; bidx[i] = 0; }

    for (int c0 = 0; c0 < KCODES; c0 += BN) {
        // packed accumulators: acc2[i][j2] holds codes (tx*8+2*j2, tx*8+2*j2+1)
        unsigned long long acc2[8][4];
        #pragma unroll
        for (int i = 0; i < 8; i++)
            #pragma unroll
            for (int j2 = 0; j2 < 4; j2++) acc2[i][j2] = 0ULL;

        for (int d0 = 0; d0 < DDIM; d0 += BK) {
            float4 breg[4];
            #pragma unroll
            for (int it = 0; it < 4; it++) {
                int linear = it * 256 + t;
                int row = linear >> 3;
                int dq  = linear & 7;
                breg[it] = *(const float4*)(emb + (size_t)(c0 + row) * DDIM + d0 + dq * 4);
            }
            __syncthreads();
            #pragma unroll
            for (int it = 0; it < 4; it++) {
                int linear = it * 256 + t;
                int row = linear >> 3;
                int dq  = linear & 7;
                Bs[(dq * 4 + 0) * APAD + row] = breg[it].x;
                Bs[(dq * 4 + 1) * APAD + row] = breg[it].y;
                Bs[(dq * 4 + 2) * APAD + row] = breg[it].z;
                Bs[(dq * 4 + 3) * APAD + row] = breg[it].w;
            }
            __syncthreads();

            #pragma unroll
            for (int k = 0; k < BK; k++) {
                float4 av0 = *(float4*)&As[(d0 + k) * APAD + ty * 8];
                float4 av1 = *(float4*)&As[(d0 + k) * APAD + ty * 8 + 4];
                float4 bv0 = *(float4*)&Bs[k * APAD + tx * 8];
                float4 bv1 = *(float4*)&Bs[k * APAD + tx * 8 + 4];

                // b pairs: adjacent codes packed into u64
                unsigned long long b2[4];
                PACK2(b2[0], __float_as_uint(bv0.x), __float_as_uint(bv0.y));
                PACK2(b2[1], __float_as_uint(bv0.z), __float_as_uint(bv0.w));
                PACK2(b2[2], __float_as_uint(bv1.x), __float_as_uint(bv1.y));
                PACK2(b2[3], __float_as_uint(bv1.z), __float_as_uint(bv1.w));

                // a broadcast pairs
                float a[8];
                a[0]=av0.x; a[1]=av0.y; a[2]=av0.z; a[3]=av0.w;
                a[4]=av1.x; a[5]=av1.y; a[6]=av1.z; a[7]=av1.w;
                unsigned long long a2[8];
                #pragma unroll
                for (int i = 0; i < 8; i++) {
                    unsigned au = __float_as_uint(a[i]);
                    PACK2(a2[i], au, au);
                }

                #pragma unroll
                for (int i = 0; i < 8; i++)
                    #pragma unroll
                    for (int j2 = 0; j2 < 4; j2++)
                        FMA_F32X2(acc2[i][j2], a2[i], b2[j2], acc2[i][j2]);
            }
        }

        // Unpack and fold into running argmin (reference-exact rounding):
        //   A = fl(xn2 + en2);  d = fma(-2, dot, A)  == fl(A - 2m)
        #pragma unroll
        for (int j2 = 0; j2 < 4; j2++) {
            int code0 = c0 + tx * 8 + 2 * j2;
            float en0 = sen[code0];
            float en1 = sen[code0 + 1];
            #pragma unroll
            for (int i = 0; i < 8; i++) {
                unsigned lo, hi;
                UNPACK2(lo, hi, acc2[i][j2]);
                float m0 = __uint_as_float(lo);
                float m1 = __uint_as_float(hi);
                float A0 = myxn2[i] + en0;
                float A1 = myxn2[i] + en1;
                float d0v = fmaf(-2.f, m0, A0);
                float d1v = fmaf(-2.f, m1, A1);
                if (d0v < best[i]) { best[i] = d0v; bidx[i] = code0; }
                if (d1v < best[i]) { best[i] = d1v; bidx[i] = code0 + 1; }
            }
        }
    }

    // ---- Cross-thread argmin: packed (float bits, code) u64 min ----
    __syncthreads();
    unsigned long long* redp = (unsigned long long*)As;  // 128*16 u64 = 16KB
    #pragma unroll
    for (int i = 0; i < 8; i++) {
        int token = ty * 8 + i;
        unsigned long long p =
            ((unsigned long long)__float_as_uint(best[i]) << 32) | (unsigned)bidx[i];
        redp[token * 16 + tx] = p;
    }
    __syncthreads();

    float part = 0.f;
    if (t < BM) {
        unsigned long long bp = redp[t * 16];
        #pragma unroll
        for (int u = 1; u < 16; u++) {
            unsigned long long p = redp[t * 16 + u];
            if (p < bp) bp = p;
        }
        int   bi = (int)(bp & 0xffffffffu);
        float bv = __uint_as_float((unsigned)(bp >> 32));
        g_idx[base + t] = bi;
        part = bv;            // d* = ||x - e*||^2
    }

    __shared__ float wsum[8];
    #pragma unroll
    for (int o = 16; o > 0; o >>= 1) part += __shfl_down_sync(0xffffffffu, part, o);
    if ((t & 31) == 0) wsum[t >> 5] = part;
    __syncthreads();
    if (t == 0) {
        float s = 0.f;
        #pragma unroll
        for (int i = 0; i < 8; i++) s += wsum[i];
        g_partial[blockIdx.x] = s;
    }
}

// ---------------------------------------------------------------------------
// Kernel 2: gather codebook rows, write transposed output, histogram
// ---------------------------------------------------------------------------
__global__ void __launch_bounds__(256, 1)
k_gather(const float* __restrict__ emb, float* __restrict__ out) {
    extern __shared__ float rows[];      // 128 * 257 floats
    __shared__ int sidx[BM];

    const int t    = threadIdx.x;
    const int base = blockIdx.x * BM;

    if (t < BM) {
        int id = g_idx[base + t];
        sidx[t] = id;
        atomicAdd(&g_counts[id], 1);
    }
    __syncthreads();

    const int w = t >> 5, lane = t & 31;
    for (int r = w; r < BM; r += 8) {
        const float* er = emb + (size_t)sidx[r] * DDIM;
        #pragma unroll
        for (int q = 0; q < 8; q++)
            rows[r * 257 + lane + q * 32] = er[lane + q * 32];
    }
    __syncthreads();

    const int b   = base >> 10;
    const int hw0 = base & 1023;
    float* ob = out + (size_t)b * (DDIM * HW) + hw0;
    const int m  = t & 127;
    const int ch = t >> 7;
    #pragma unroll 4
    for (int cc = 0; cc < 128; cc++) {
        int c = cc * 2 + ch;
        ob[(size_t)c * HW + m] = rows[m * 257 + c];
    }
}

// ---------------------------------------------------------------------------
// Kernel 3: loss reduce + perplexity
// ---------------------------------------------------------------------------
__global__ void k_final(float* __restrict__ out) {
    __shared__ float sh[1024];
    const int t = threadIdx.x;

    float s = (t < NB1) ? g_partial[t] : 0.f;
    sh[t] = s; __syncthreads();
    for (int o = 512; o > 0; o >>= 1) {
        if (t < o) sh[t] += sh[t + o];
        __syncthreads();
    }
    if (t == 0) out[OUT_ELEMS] = 1.25f * sh[0] / 16777216.0f;
    __syncthreads();

    float e = 0.f;
    for (int k = t; k < KCODES; k += 1024) {
        float p = (float)g_counts[k] * (1.0f / 65536.0f);
        e -= p * logf(p + 1e-10f);
    }
    sh[t] = e; __syncthreads();
    for (int o = 512; o > 0; o >>= 1) {
        if (t < o) sh[t] += sh[t + o];
        __syncthreads();
    }
    if (t == 0) out[OUT_ELEMS + 1] = expf(sh[0]);
}

// ---------------------------------------------------------------------------
extern "C" void kernel_launch(void* const* d_in, const int* in_sizes, int n_in,
                              void* d_out, int out_size) {
    const float* x   = (const float*)d_in[0];
    const float* emb = (const float*)d_in[1];
    float* out = (float*)d_out;

    const int SMEM1 = (DDIM * APAD + BK * APAD + KCODES) * sizeof(float); // ~168 KB
    const int SMEM2 = BM * 257 * sizeof(float);                           // ~132 KB
    cudaFuncSetAttribute(k_argmin, cudaFuncAttributeMaxDynamicSharedMemorySize, SMEM1);
    cudaFuncSetAttribute(k_gather, cudaFuncAttributeMaxDynamicSharedMemorySize, SMEM2);

    k_prep  <<<KCODES, 256>>>(emb);
    k_argmin<<<NB1,    256, SMEM1>>>(x, emb);
    k_gather<<<NB1,    256, SMEM2>>>(emb, out);
    k_final <<<1,     1024>>>(out);
}

// round 7
// speedup vs baseline: 3.0633x; 3.0633x over previous
#include <cuda_runtime.h>
#include <cuda_bf16.h>
#include <math.h>
#include <stdint.h>

#define TOKENS   65536
#define DDIM     256
#define KCODES   4096
#define HW       1024
#define OUT_ELEMS 16777216
#define NBMMA    512             // 128 tokens per CTA
#define NBRES    8192            // 8 tokens per CTA
typedef unsigned long long u64;

// ---------------- global scratch ----------------
// fragment-major bf16 A: [mt(4096)][kt(16)][lane(32)][4]u32
__device__ uint32_t g_x1f[TOKENS / 16 * 16 * 32 * 4];
// fragment-major bf16 B: [nt(32)][nb(16)][kt(16)][lane(32)][2]u32
__device__ uint32_t g_e1f[KCODES / 128 * 16 * 16 * 32 * 2];
__device__ float g_xT[TOKENS * DDIM];    // token-major fp32 x (rescore)
__device__ float g_xn2[TOKENS];
__device__ float g_enorm2[KCODES];
__device__ int   g_cand[TOKENS * 8];
__device__ int   g_idx[TOKENS];
__device__ float g_partial[NBRES];
__device__ int   g_counts[KCODES];

#define CP_ASYNC16(dst, src) \
    asm volatile("cp.async.cg.shared.global [%0], [%1], 16;" :: "r"(dst), "l"(src))
#define CP_COMMIT()  asm volatile("cp.async.commit_group;" ::: "memory")
#define CP_WAIT_0()  asm volatile("cp.async.wait_group 0;" ::: "memory")
#define CP_WAIT_1()  asm volatile("cp.async.wait_group 1;" ::: "memory")

__device__ __forceinline__ uint32_t su32(const void* p) {
    uint32_t a;
    asm("{ .reg .u64 t; cvta.to.shared.u64 t, %1; cvt.u32.u64 %0, t; }"
        : "=r"(a) : "l"(p));
    return a;
}
__device__ __forceinline__ uint32_t pack_bf2(float lo, float hi) {
    // low 16 bits = element with smaller k index
    uint32_t l = (uint32_t)__bfloat16_as_ushort(__float2bfloat16(lo));
    uint32_t h = (uint32_t)__bfloat16_as_ushort(__float2bfloat16(hi));
    return l | (h << 16);
}
__device__ __forceinline__ void mma16816(float* c, const uint32_t* a, const uint32_t* b) {
    asm volatile(
        "mma.sync.aligned.m16n8k16.row.col.f32.bf16.bf16.f32 "
        "{%0,%1,%2,%3},{%4,%5,%6,%7},{%8,%9},{%0,%1,%2,%3};"
        : "+f"(c[0]), "+f"(c[1]), "+f"(c[2]), "+f"(c[3])
        : "r"(a[0]), "r"(a[1]), "r"(a[2]), "r"(a[3]), "r"(b[0]), "r"(b[1]));
}
__device__ __forceinline__ void ins6(u64 p, u64* s) {
    if (p >= s[5]) return;
    s[5] = p;
    if (s[5] < s[4]) { u64 t = s[4]; s[4] = s[5]; s[5] = t; }
    if (s[4] < s[3]) { u64 t = s[3]; s[3] = s[4]; s[4] = t; }
    if (s[3] < s[2]) { u64 t = s[2]; s[2] = s[3]; s[3] = t; }
    if (s[2] < s[1]) { u64 t = s[1]; s[1] = s[2]; s[2] = t; }
    if (s[1] < s[0]) { u64 t = s[0]; s[0] = s[1]; s[1] = t; }
}
__device__ __forceinline__ void ins8(u64 p, u64* s) {
    if (p >= s[7]) return;
    s[7] = p;
    #pragma unroll
    for (int i = 7; i > 0; i--)
        if (s[i] < s[i-1]) { u64 t = s[i-1]; s[i-1] = s[i]; s[i] = t; }
}

// ---------------------------------------------------------------------------
// Prep E: fragment-major bf16 codebook + |e|^2 + zero histogram
// block = 128 threads, one code row
// ---------------------------------------------------------------------------
__global__ void k_prep_e(const float* __restrict__ emb) {
    const int n = blockIdx.x, q = threadIdx.x;     // q = k-pair 0..127
    float v0 = emb[(size_t)n * DDIM + 2 * q];
    float v1 = emb[(size_t)n * DDIM + 2 * q + 1];
    // B frag coords: col gid = n&7, b-reg = ((q&7)>=4), tig = q&3, kt = q>>3
    int nt = n >> 7, nb = (n >> 3) & 15, gid = n & 7;
    int kt = q >> 3, reg = ((q & 7) >> 2), tig = q & 3;
    int lane = gid * 4 + tig;
    g_e1f[(((nt * 16 + nb) * 16 + kt) * 32 + lane) * 2 + reg] = pack_bf2(v0, v1);

    float s = v0 * v0 + v1 * v1;
    __shared__ float red[4];
    #pragma unroll
    for (int o = 16; o > 0; o >>= 1) s += __shfl_down_sync(0xffffffffu, s, o);
    if ((q & 31) == 0) red[q >> 5] = s;
    __syncthreads();
    if (q == 0) {
        g_enorm2[n] = red[0] + red[1] + red[2] + red[3];
        g_counts[n] = 0;
    }
}

// ---------------------------------------------------------------------------
// Prep X: transpose tile, |x|^2, token-major fp32, fragment-major bf16
// ---------------------------------------------------------------------------
__global__ void __launch_bounds__(256, 1) k_prep_x(const float* __restrict__ x) {
    extern __shared__ float As[];   // [d][m] 256*132
    const int t = threadIdx.x;
    const int base = blockIdx.x * 128;
    const int b = base >> 10, hw0 = base & 1023;
    const float* xb = x + (size_t)b * (DDIM * HW) + hw0;
    {
        int lane4 = (t & 31) * 4, d0 = t >> 5;
        #pragma unroll
        for (int dd = 0; dd < DDIM; dd += 8) {
            int d = dd + d0;
            float4 v = *(const float4*)(xb + (size_t)d * HW + lane4);
            *(float4*)&As[d * 132 + lane4] = v;
        }
    }
    __syncthreads();
    if (t < 128) {
        float s = 0.f;
        #pragma unroll 8
        for (int d = 0; d < DDIM; d++) { float v = As[d * 132 + t]; s = fmaf(v, v, s); }
        g_xn2[base + t] = s;
    }
    // token-major fp32 copy (rescore input)
    for (int i = t; i < 128 * 256; i += 256) {
        int m = i >> 8, d = i & 255;
        g_xT[(size_t)(base + m) * DDIM + d] = As[d * 132 + m];
    }
    // fragment-major bf16: A frag coords
    for (int i = t; i < 128 * 128; i += 256) {
        int m = i >> 7, q = i & 127;             // token-local, k-pair
        float v0 = As[(2 * q) * 132 + m];
        float v1 = As[(2 * q + 1) * 132 + m];
        int mt = (base + m) >> 4;
        int r = m & 15, gid = r & 7, rsel = r >> 3;
        int kt = q >> 3, reg = rsel + (((q & 7) >> 2) << 1), tig = q & 3;
        int lane = gid * 4 + tig;
        g_x1f[((mt * 16 + kt) * 32 + lane) * 4 + reg] = pack_bf2(v0, v1);
    }
}

// ---------------------------------------------------------------------------
// Main: bf16 mma.sync distance GEMM + top-8 candidate capture
// SMEM: A frags 64KB @0, B double buffer 2x64KB @65536
// ---------------------------------------------------------------------------
__global__ void __launch_bounds__(256, 1) k_mma() {
    extern __shared__ char sm[];
    const uint32_t smb = su32(sm);
    const int t = threadIdx.x, wid = t >> 5, lane = t & 31;
    const int gid = lane >> 2, tig = lane & 3;
    const int base = blockIdx.x * 128;

    // load resident A frags: 64KB contiguous
    {
        const char* src = (const char*)g_x1f + (size_t)(base >> 4) * 8192;
        #pragma unroll
        for (int j = 0; j < 16; j++) {
            int i = t + j * 256;
            CP_ASYNC16(smb + i * 16, src + i * 16);
        }
    }
    CP_COMMIT();
    // prefetch B ntile 0
    {
        const char* src = (const char*)g_e1f;
        #pragma unroll
        for (int j = 0; j < 16; j++) {
            int i = t + j * 256;
            CP_ASYNC16(smb + 65536 + i * 16, src + i * 16);
        }
    }
    CP_COMMIT();

    const float xr0 = g_xn2[base + wid * 16 + gid];
    const float xr1 = g_xn2[base + wid * 16 + gid + 8];
    u64 s0[6], s1[6];
    #pragma unroll
    for (int i = 0; i < 6; i++) { s0[i] = ~0ULL; s1[i] = ~0ULL; }

    const uint32_t* Af = (const uint32_t*)sm;

    for (int nt = 0; nt < 32; nt++) {
        if (nt + 1 < 32) {
            const char* src = (const char*)g_e1f + (size_t)(nt + 1) * 65536;
            uint32_t dst = smb + 65536 + ((nt + 1) & 1) * 65536;
            #pragma unroll
            for (int j = 0; j < 16; j++) {
                int i = t + j * 256;
                CP_ASYNC16(dst + i * 16, src + i * 16);
            }
            CP_COMMIT();
            CP_WAIT_1();
        } else {
            CP_WAIT_0();
        }
        __syncthreads();

        const uint32_t* Bf = (const uint32_t*)(sm + 65536 + (nt & 1) * 65536);
        float acc[16][4];
        #pragma unroll
        for (int nb = 0; nb < 16; nb++)
            #pragma unroll
            for (int c = 0; c < 4; c++) acc[nb][c] = 0.f;

        #pragma unroll 4
        for (int kt = 0; kt < 16; kt++) {
            uint32_t a[4];
            *(uint4*)a = *(const uint4*)&Af[((wid * 16 + kt) * 32 + lane) * 4];
            #pragma unroll
            for (int nb = 0; nb < 16; nb++) {
                uint32_t bfr[2];
                *(uint2*)bfr = *(const uint2*)&Bf[((nb * 16 + kt) * 32 + lane) * 2];
                mma16816(acc[nb], a, bfr);
            }
        }

        // fold into per-thread top-6 (codes ascending => stable lowest-index bias)
        #pragma unroll
        for (int nb = 0; nb < 16; nb++) {
            int code0 = nt * 128 + nb * 8 + tig * 2;
            float en0 = __ldg(&g_enorm2[code0]);
            float en1 = __ldg(&g_enorm2[code0 + 1]);
            float d00 = fmaf(-2.f, acc[nb][0], xr0 + en0);
            float d01 = fmaf(-2.f, acc[nb][1], xr0 + en1);
            float d10 = fmaf(-2.f, acc[nb][2], xr1 + en0);
            float d11 = fmaf(-2.f, acc[nb][3], xr1 + en1);
            ins6(((u64)__float_as_uint(d00) << 32) | (unsigned)code0,       s0);
            ins6(((u64)__float_as_uint(d01) << 32) | (unsigned)(code0 + 1), s0);
            ins6(((u64)__float_as_uint(d10) << 32) | (unsigned)code0,       s1);
            ins6(((u64)__float_as_uint(d11) << 32) | (unsigned)(code0 + 1), s1);
        }
        __syncthreads();
    }

    // merge: 4 owner lanes x top-6 -> top-8 per token
    u64* cm = (u64*)(sm + 65536);     // [128][24]
    {
        int tok0 = wid * 16 + gid;
        #pragma unroll
        for (int i = 0; i < 6; i++) cm[tok0 * 24 + tig * 6 + i] = s0[i];
        int tok1 = tok0 + 8;
        #pragma unroll
        for (int i = 0; i < 6; i++) cm[tok1 * 24 + tig * 6 + i] = s1[i];
    }
    __syncthreads();
    if (t < 128) {
        u64 top[8];
        #pragma unroll
        for (int i = 0; i < 8; i++) top[i] = ~0ULL;
        #pragma unroll
        for (int i = 0; i < 24; i++) ins8(cm[t * 24 + i], top);
        #pragma unroll
        for (int i = 0; i < 8; i++)
            g_cand[(size_t)(base + t) * 8 + i] = (int)(top[i] & 0xffffffffu);
    }
}

// ---------------------------------------------------------------------------
// Rescore: exact fp32 distance for 8 candidates per token (warp per token)
// Reference chain: d = fma(-2, dot, fl(xn2 + en2)); lowest-index u64 tie-break.
// ---------------------------------------------------------------------------
__global__ void __launch_bounds__(256, 4) k_rescore(const float* __restrict__ emb) {
    const int t = threadIdx.x, wid = t >> 5, lane = t & 31;
    const int n = blockIdx.x * 8 + wid;
    const float4* xr = (const float4*)(g_xT + (size_t)n * DDIM + lane * 8);
    float4 xa = xr[0], xb = xr[1];
    float xn2 = g_xn2[n];
    u64 best = ~0ULL;
    #pragma unroll
    for (int i = 0; i < 8; i++) {
        int c = g_cand[(size_t)n * 8 + i];
        const float4* er = (const float4*)(emb + (size_t)c * DDIM + lane * 8);
        float4 ea = er[0], eb = er[1];
        float p = 0.f;
        p = fmaf(xa.x, ea.x, p); p = fmaf(xa.y, ea.y, p);
        p = fmaf(xa.z, ea.z, p); p = fmaf(xa.w, ea.w, p);
        p = fmaf(xb.x, eb.x, p); p = fmaf(xb.y, eb.y, p);
        p = fmaf(xb.z, eb.z, p); p = fmaf(xb.w, eb.w, p);
        #pragma unroll
        for (int o = 16; o > 0; o >>= 1) p += __shfl_xor_sync(0xffffffffu, p, o);
        float A = xn2 + __ldg(&g_enorm2[c]);
        float d = fmaf(-2.f, p, A);
        u64 pk = ((u64)__float_as_uint(d) << 32) | (unsigned)c;
        if (pk < best) best = pk;
    }
    __shared__ float wb[8];
    if (lane == 0) {
        g_idx[n] = (int)(best & 0xffffffffu);
        wb[wid] = __uint_as_float((unsigned)(best >> 32));
    }
    __syncthreads();
    if (t == 0) {
        float s = 0.f;
        #pragma unroll
        for (int i = 0; i < 8; i++) s += wb[i];
        g_partial[blockIdx.x] = s;
    }
}

// ---------------------------------------------------------------------------
// Gather + histogram
// ---------------------------------------------------------------------------
__global__ void __launch_bounds__(256, 1)
k_gather(const float* __restrict__ emb, float* __restrict__ out) {
    extern __shared__ float rows[];      // 128 * 257
    __shared__ int sidx[128];
    const int t = threadIdx.x;
    const int base = blockIdx.x * 128;
    if (t < 128) {
        int id = g_idx[base + t];
        sidx[t] = id;
        atomicAdd(&g_counts[id], 1);
    }
    __syncthreads();
    const int w = t >> 5, lane = t & 31;
    for (int r = w; r < 128; r += 8) {
        const float* er = emb + (size_t)sidx[r] * DDIM;
        #pragma unroll
        for (int q = 0; q < 8; q++)
            rows[r * 257 + lane + q * 32] = er[lane + q * 32];
    }
    __syncthreads();
    const int b = base >> 10, hw0 = base & 1023;
    float* ob = out + (size_t)b * (DDIM * HW) + hw0;
    const int m = t & 127, ch = t >> 7;
    #pragma unroll 4
    for (int cc = 0; cc < 128; cc++) {
        int c = cc * 2 + ch;
        ob[(size_t)c * HW + m] = rows[m * 257 + c];
    }
}

// ---------------------------------------------------------------------------
// Loss + perplexity
// ---------------------------------------------------------------------------
__global__ void k_final(float* __restrict__ out) {
    __shared__ float sh[1024];
    const int t = threadIdx.x;
    float s = 0.f;
    for (int i = t; i < NBRES; i += 1024) s += g_partial[i];
    sh[t] = s; __syncthreads();
    for (int o = 512; o > 0; o >>= 1) {
        if (t < o) sh[t] += sh[t + o];
        __syncthreads();
    }
    if (t == 0) out[OUT_ELEMS] = 1.25f * sh[0] / 16777216.0f;
    __syncthreads();
    float e = 0.f;
    for (int k = t; k < KCODES; k += 1024) {
        float p = (float)g_counts[k] * (1.0f / 65536.0f);
        e -= p * logf(p + 1e-10f);
    }
    sh[t] = e; __syncthreads();
    for (int o = 512; o > 0; o >>= 1) {
        if (t < o) sh[t] += sh[t + o];
        __syncthreads();
    }
    if (t == 0) out[OUT_ELEMS + 1] = expf(sh[0]);
}

// ---------------------------------------------------------------------------
extern "C" void kernel_launch(void* const* d_in, const int* in_sizes, int n_in,
                              void* d_out, int out_size) {
    const float* x   = (const float*)d_in[0];
    const float* emb = (const float*)d_in[1];
    float* out = (float*)d_out;

    const int SMEMX = 256 * 132 * sizeof(float);   // 135168
    const int SMEMM = 65536 + 2 * 65536;           // 196608
    const int SMEMG = 128 * 257 * sizeof(float);   // 131584
    cudaFuncSetAttribute(k_prep_x, cudaFuncAttributeMaxDynamicSharedMemorySize, SMEMX);
    cudaFuncSetAttribute(k_mma,    cudaFuncAttributeMaxDynamicSharedMemorySize, SMEMM);
    cudaFuncSetAttribute(k_gather, cudaFuncAttributeMaxDynamicSharedMemorySize, SMEMG);

    k_prep_e <<<KCODES, 128>>>(emb);
    k_prep_x <<<TOKENS / 128, 256, SMEMX>>>(x);
    k_mma    <<<NBMMA, 256, SMEMM>>>();
    k_rescore<<<NBRES, 256>>>(emb);
    k_gather <<<TOKENS / 128, 256, SMEMG>>>(emb, out);
    k_final  <<<1, 1024>>>(out);
}

// round 9
// speedup vs baseline: 3.1939x; 1.0426x over previous
#include <cuda_runtime.h>
#include <cuda_bf16.h>
#include <math.h>
#include <stdint.h>

#define TOKENS   65536
#define DDIM     256
#define KCODES   4096
#define HW       1024
#define OUT_ELEMS 16777216
#define NBMMA    512             // 128 tokens per CTA
#define NBRES    8192            // 8 tokens per CTA
#define BPAD     36              // padded u32 per (kt,lane) in B smem (32 data + 4 pad)
#define BSTAGE   (16 * 32 * BPAD * 4)   // 73728 bytes per B buffer
typedef unsigned long long u64;

// ---------------- global scratch ----------------
// fragment-major bf16 A: [mt(4096)][kt(16)][lane(32)][4] u32
__device__ uint32_t g_x1f[4096 * 16 * 32 * 4];
// fragment-major bf16 B: [nt(32)][kt(16)][lane(32)][nb(16)*2] u32
__device__ uint32_t g_e1f[32 * 16 * 32 * 32];
__device__ float g_xT[TOKENS * DDIM];    // token-major fp32 x (rescore)
__device__ float g_xn2[TOKENS];
__device__ float g_enorm2[KCODES];
__device__ int   g_cand[TOKENS * 8];
__device__ int   g_idx[TOKENS];
__device__ float g_partial[NBRES];
__device__ int   g_counts[KCODES];

#define CP_ASYNC16(dst, src) \
    asm volatile("cp.async.cg.shared.global [%0], [%1], 16;" :: "r"(dst), "l"(src))
#define CP_COMMIT()  asm volatile("cp.async.commit_group;" ::: "memory")
#define CP_WAIT_0()  asm volatile("cp.async.wait_group 0;" ::: "memory")
#define CP_WAIT_1()  asm volatile("cp.async.wait_group 1;" ::: "memory")

__device__ __forceinline__ uint32_t su32(const void* p) {
    uint32_t a;
    asm("{ .reg .u64 t; cvta.to.shared.u64 t, %1; cvt.u32.u64 %0, t; }"
        : "=r"(a) : "l"(p));
    return a;
}
__device__ __forceinline__ uint32_t pack_bf2(float lo, float hi) {
    uint32_t l = (uint32_t)__bfloat16_as_ushort(__float2bfloat16(lo));
    uint32_t h = (uint32_t)__bfloat16_as_ushort(__float2bfloat16(hi));
    return l | (h << 16);
}
__device__ __forceinline__ void mma16816(float* c, const uint32_t* a, const uint32_t* b) {
    asm volatile(
        "mma.sync.aligned.m16n8k16.row.col.f32.bf16.bf16.f32 "
        "{%0,%1,%2,%3},{%4,%5,%6,%7},{%8,%9},{%0,%1,%2,%3};"
        : "+f"(c[0]), "+f"(c[1]), "+f"(c[2]), "+f"(c[3])
        : "r"(a[0]), "r"(a[1]), "r"(a[2]), "r"(a[3]), "r"(b[0]), "r"(b[1]));
}
__device__ __forceinline__ void ins5(u64 p, u64* s) {
    if (p >= s[4]) return;
    s[4] = p;
    if (s[4] < s[3]) { u64 t = s[3]; s[3] = s[4]; s[4] = t; }
    if (s[3] < s[2]) { u64 t = s[2]; s[2] = s[3]; s[3] = t; }
    if (s[2] < s[1]) { u64 t = s[1]; s[1] = s[2]; s[2] = t; }
    if (s[1] < s[0]) { u64 t = s[0]; s[0] = s[1]; s[1] = t; }
}
__device__ __forceinline__ void ins8(u64 p, u64* s) {
    if (p >= s[7]) return;
    s[7] = p;
    #pragma unroll
    for (int i = 7; i > 0; i--)
        if (s[i] < s[i-1]) { u64 t = s[i-1]; s[i-1] = s[i]; s[i] = t; }
}

// ---------------------------------------------------------------------------
// Prep E: one n-tile (128 codes) per CTA; coalesced frag writes; |e|^2; hist=0
// ---------------------------------------------------------------------------
__global__ void __launch_bounds__(256, 1) k_prep_e(const float* __restrict__ emb) {
    extern __shared__ float sp[];          // [128][260]
    const int t = threadIdx.x, nt = blockIdx.x;
    const float* src = emb + (size_t)nt * 128 * DDIM;
    #pragma unroll
    for (int j = 0; j < 32; j++) {
        int i = t + j * 256;               // 0..8191 float4s
        int row = i >> 6, c4 = i & 63;
        float4 v = *(const float4*)(src + row * DDIM + c4 * 4);
        *(float4*)&sp[row * 260 + c4 * 4] = v;
    }
    __syncthreads();
    if (t < 128) {
        float s = 0.f;
        #pragma unroll 8
        for (int d = 0; d < DDIM; d++) { float v = sp[t * 260 + d]; s = fmaf(v, v, s); }
        g_enorm2[nt * 128 + t] = s;
        g_counts[nt * 128 + t] = 0;
    }
    // destination-major frag build: i = kt*1024 + lane*32 + nb*2 + reg
    uint32_t* dst = g_e1f + (size_t)nt * 16384;
    #pragma unroll
    for (int j = 0; j < 64; j++) {
        int i = t + j * 256;
        int reg = i & 1, nb = (i >> 1) & 15, lane = (i >> 5) & 31, kt = i >> 10;
        int gid = lane >> 2, tig = lane & 3;
        int nl = nb * 8 + gid;
        int q = kt * 8 + reg * 4 + tig;    // k-pair
        dst[i] = pack_bf2(sp[nl * 260 + 2 * q], sp[nl * 260 + 2 * q + 1]);
    }
}

// ---------------------------------------------------------------------------
// Prep X: transpose, |x|^2, fp32 token-major, coalesced frag writes
// ---------------------------------------------------------------------------
__global__ void __launch_bounds__(256, 1) k_prep_x(const float* __restrict__ x) {
    extern __shared__ float As[];   // [d][m] 256*132
    const int t = threadIdx.x;
    const int base = blockIdx.x * 128;
    const int b = base >> 10, hw0 = base & 1023;
    const float* xb = x + (size_t)b * (DDIM * HW) + hw0;
    {
        int lane4 = (t & 31) * 4, d0 = t >> 5;
        #pragma unroll
        for (int dd = 0; dd < DDIM; dd += 8) {
            int d = dd + d0;
            float4 v = *(const float4*)(xb + (size_t)d * HW + lane4);
            *(float4*)&As[d * 132 + lane4] = v;
        }
    }
    __syncthreads();
    if (t < 128) {
        float s = 0.f;
        #pragma unroll 8
        for (int d = 0; d < DDIM; d++) { float v = As[d * 132 + t]; s = fmaf(v, v, s); }
        g_xn2[base + t] = s;
    }
    for (int i = t; i < 128 * 256; i += 256) {
        int m = i >> 8, d = i & 255;
        g_xT[(size_t)(base + m) * DDIM + d] = As[d * 132 + m];
    }
    // destination-major frags: i = mtl*2048 + kt*128 + lane*4 + reg
    // FIX: 128 u32 per token  ->  block offset = base * 128 u32 (= base*512 bytes)
    uint32_t* dst = g_x1f + (size_t)base * 128;
    #pragma unroll
    for (int j = 0; j < 64; j++) {
        int i = t + j * 256;
        int reg = i & 3, lane = (i >> 2) & 31, kt = (i >> 7) & 15, mtl = i >> 11;
        int gid = lane >> 2, tig = lane & 3;
        int rsel = reg & 1, khalf = reg >> 1;
        int m = mtl * 16 + rsel * 8 + gid;
        int q = kt * 8 + khalf * 4 + tig;
        dst[i] = pack_bf2(As[(2 * q) * 132 + m], As[(2 * q + 1) * 132 + m]);
    }
}

// ---------------------------------------------------------------------------
// Main: bf16 mma.sync, 2mt x 8nb per warp, padded-B smem, top-5 lists
// SMEM: A 64KB @0, B double buffer 2 x 73728B @65536
// ---------------------------------------------------------------------------
__device__ __forceinline__ void load_b(uint32_t smb, int nt, int t) {
    const char* src = (const char*)g_e1f + (size_t)nt * 65536;
    uint32_t dst = smb + 65536 + (nt & 1) * BSTAGE;
    #pragma unroll
    for (int j = 0; j < 16; j++) {
        int c = t + j * 256;               // 0..4095 16B chunks
        int kt = c >> 8, ln = (c >> 3) & 31, jj = c & 7;
        CP_ASYNC16(dst + ((kt * 32 + ln) * BPAD + jj * 4) * 4, src + c * 16);
    }
}

__global__ void __launch_bounds__(256, 1) k_mma() {
    extern __shared__ char sm[];
    const uint32_t smb = su32(sm);
    const int t = threadIdx.x, wid = t >> 5, lane = t & 31;
    const int gid = lane >> 2, tig = lane & 3;
    const int base = blockIdx.x * 128;
    const int mt0 = (wid & 3) * 2, mt1 = mt0 + 1;   // local m-tiles
    const int h = wid >> 2;                          // nb half 0/1

    // resident A frags: 64KB contiguous
    // FIX: block offset = base * 512 bytes (128 u32 per token)
    {
        const char* src = (const char*)g_x1f + (size_t)base * 512;
        #pragma unroll
        for (int j = 0; j < 16; j++) {
            int i = t + j * 256;
            CP_ASYNC16(smb + i * 16, src + i * 16);
        }
    }
    CP_COMMIT();
    load_b(smb, 0, t); CP_COMMIT();

    const float xr00 = g_xn2[base + mt0 * 16 + gid];
    const float xr01 = g_xn2[base + mt0 * 16 + gid + 8];
    const float xr10 = g_xn2[base + mt1 * 16 + gid];
    const float xr11 = g_xn2[base + mt1 * 16 + gid + 8];

    u64 L[4][5];   // [mtsel*2+rsel][top5]
    #pragma unroll
    for (int l = 0; l < 4; l++)
        #pragma unroll
        for (int i = 0; i < 5; i++) L[l][i] = ~0ULL;

    const uint32_t* Af = (const uint32_t*)sm;

    for (int nt = 0; nt < 32; nt++) {
        __syncthreads();                       // everyone done with tile nt-1
        if (nt + 1 < 32) { load_b(smb, nt + 1, t); CP_COMMIT(); CP_WAIT_1(); }
        else             { CP_WAIT_0(); }
        __syncthreads();                       // buffer nt fully visible

        const uint32_t* Bf = (const uint32_t*)(sm + 65536 + (nt & 1) * BSTAGE);
        float acc[16][4];
        #pragma unroll
        for (int p = 0; p < 16; p++)
            #pragma unroll
            for (int c = 0; c < 4; c++) acc[p][c] = 0.f;

        #pragma unroll 4
        for (int kt = 0; kt < 16; kt++) {
            uint32_t a0[4], a1[4], bb[16];
            *(uint4*)a0 = *(const uint4*)(Af + ((mt0 * 16 + kt) * 32 + lane) * 4);
            *(uint4*)a1 = *(const uint4*)(Af + ((mt1 * 16 + kt) * 32 + lane) * 4);
            const uint32_t* bp = Bf + (kt * 32 + lane) * BPAD + h * 16;
            *(uint4*)(bb + 0)  = *(const uint4*)(bp + 0);
            *(uint4*)(bb + 4)  = *(const uint4*)(bp + 4);
            *(uint4*)(bb + 8)  = *(const uint4*)(bp + 8);
            *(uint4*)(bb + 12) = *(const uint4*)(bp + 12);
            #pragma unroll
            for (int j = 0; j < 8; j++) {
                mma16816(acc[j],     a0, bb + j * 2);
                mma16816(acc[8 + j], a1, bb + j * 2);
            }
        }

        // fold: d = fma(-2, dot, xn2 + en2); codes ascending; strict '<'
        #pragma unroll
        for (int nb2 = 0; nb2 < 8; nb2++) {
            int code0 = nt * 128 + (h * 8 + nb2) * 8 + tig * 2;
            float en0 = __ldg(&g_enorm2[code0]);
            float en1 = __ldg(&g_enorm2[code0 + 1]);
            float d;
            d = fmaf(-2.f, acc[nb2][0],     xr00 + en0);
            ins5(((u64)__float_as_uint(d) << 32) | (unsigned)code0,       L[0]);
            d = fmaf(-2.f, acc[nb2][1],     xr00 + en1);
            ins5(((u64)__float_as_uint(d) << 32) | (unsigned)(code0 + 1), L[0]);
            d = fmaf(-2.f, acc[nb2][2],     xr01 + en0);
            ins5(((u64)__float_as_uint(d) << 32) | (unsigned)code0,       L[1]);
            d = fmaf(-2.f, acc[nb2][3],     xr01 + en1);
            ins5(((u64)__float_as_uint(d) << 32) | (unsigned)(code0 + 1), L[1]);
            d = fmaf(-2.f, acc[8 + nb2][0], xr10 + en0);
            ins5(((u64)__float_as_uint(d) << 32) | (unsigned)code0,       L[2]);
            d = fmaf(-2.f, acc[8 + nb2][1], xr10 + en1);
            ins5(((u64)__float_as_uint(d) << 32) | (unsigned)(code0 + 1), L[2]);
            d = fmaf(-2.f, acc[8 + nb2][2], xr11 + en0);
            ins5(((u64)__float_as_uint(d) << 32) | (unsigned)code0,       L[3]);
            d = fmaf(-2.f, acc[8 + nb2][3], xr11 + en1);
            ins5(((u64)__float_as_uint(d) << 32) | (unsigned)(code0 + 1), L[3]);
        }
    }

    // merge: 8 lists x top-5 per token -> top-8
    __syncthreads();
    u64* cm = (u64*)(sm + 65536);              // [128][8][5] = 40KB
    #pragma unroll
    for (int l = 0; l < 4; l++) {
        int mtl = mt0 + (l >> 1);
        int tok = mtl * 16 + (l & 1) * 8 + gid;
        #pragma unroll
        for (int i = 0; i < 5; i++)
            cm[(size_t)tok * 40 + (h * 4 + tig) * 5 + i] = L[l][i];
    }
    __syncthreads();
    if (t < 128) {
        u64 top[8];
        #pragma unroll
        for (int i = 0; i < 8; i++) top[i] = ~0ULL;
        #pragma unroll
        for (int i = 0; i < 40; i++) ins8(cm[(size_t)t * 40 + i], top);
        #pragma unroll
        for (int i = 0; i < 8; i++)
            g_cand[(size_t)(base + t) * 8 + i] = (int)(top[i] & 0xffffffffu);
    }
}

// ---------------------------------------------------------------------------
// Rescore: exact fp32 distance for 8 candidates per token (warp per token)
// ---------------------------------------------------------------------------
__global__ void __launch_bounds__(256, 4) k_rescore(const float* __restrict__ emb) {
    const int t = threadIdx.x, wid = t >> 5, lane = t & 31;
    const int n = blockIdx.x * 8 + wid;
    const float4* xr = (const float4*)(g_xT + (size_t)n * DDIM + lane * 8);
    float4 xa = xr[0], xb = xr[1];
    float xn2 = g_xn2[n];
    u64 best = ~0ULL;
    #pragma unroll
    for (int i = 0; i < 8; i++) {
        int c = g_cand[(size_t)n * 8 + i];
        const float4* er = (const float4*)(emb + (size_t)c * DDIM + lane * 8);
        float4 ea = er[0], eb = er[1];
        float p = 0.f;
        p = fmaf(xa.x, ea.x, p); p = fmaf(xa.y, ea.y, p);
        p = fmaf(xa.z, ea.z, p); p = fmaf(xa.w, ea.w, p);
        p = fmaf(xb.x, eb.x, p); p = fmaf(xb.y, eb.y, p);
        p = fmaf(xb.z, eb.z, p); p = fmaf(xb.w, eb.w, p);
        #pragma unroll
        for (int o = 16; o > 0; o >>= 1) p += __shfl_xor_sync(0xffffffffu, p, o);
        float A = xn2 + __ldg(&g_enorm2[c]);
        float d = fmaf(-2.f, p, A);
        u64 pk = ((u64)__float_as_uint(d) << 32) | (unsigned)c;
        if (pk < best) best = pk;
    }
    __shared__ float wb[8];
    if (lane == 0) {
        g_idx[n] = (int)(best & 0xffffffffu);
        wb[wid] = __uint_as_float((unsigned)(best >> 32));
    }
    __syncthreads();
    if (t == 0) {
        float s = 0.f;
        #pragma unroll
        for (int i = 0; i < 8; i++) s += wb[i];
        g_partial[blockIdx.x] = s;
    }
}

// ---------------------------------------------------------------------------
// Gather + histogram
// ---------------------------------------------------------------------------
__global__ void __launch_bounds__(256, 1)
k_gather(const float* __restrict__ emb, float* __restrict__ out) {
    extern __shared__ float rows[];      // 128 * 257
    __shared__ int sidx[128];
    const int t = threadIdx.x;
    const int base = blockIdx.x * 128;
    if (t < 128) {
        int id = g_idx[base + t];
        sidx[t] = id;
        atomicAdd(&g_counts[id], 1);
    }
    __syncthreads();
    const int w = t >> 5, lane = t & 31;
    for (int r = w; r < 128; r += 8) {
        const float* er = emb + (size_t)sidx[r] * DDIM;
        #pragma unroll
        for (int q = 0; q < 8; q++)
            rows[r * 257 + lane + q * 32] = er[lane + q * 32];
    }
    __syncthreads();
    const int b = base >> 10, hw0 = base & 1023;
    float* ob = out + (size_t)b * (DDIM * HW) + hw0;
    const int m = t & 127, ch = t >> 7;
    #pragma unroll 4
    for (int cc = 0; cc < 128; cc++) {
        int c = cc * 2 + ch;
        ob[(size_t)c * HW + m] = rows[m * 257 + c];
    }
}

// ---------------------------------------------------------------------------
// Loss + perplexity
// ---------------------------------------------------------------------------
__global__ void k_final(float* __restrict__ out) {
    __shared__ float sh[1024];
    const int t = threadIdx.x;
    float s = 0.f;
    for (int i = t; i < NBRES; i += 1024) s += g_partial[i];
    sh[t] = s; __syncthreads();
    for (int o = 512; o > 0; o >>= 1) {
        if (t < o) sh[t] += sh[t + o];
        __syncthreads();
    }
    if (t == 0) out[OUT_ELEMS] = 1.25f * sh[0] / 16777216.0f;
    __syncthreads();
    float e = 0.f;
    for (int k = t; k < KCODES; k += 1024) {
        float p = (float)g_counts[k] * (1.0f / 65536.0f);
        e -= p * logf(p + 1e-10f);
    }
    sh[t] = e; __syncthreads();
    for (int o = 512; o > 0; o >>= 1) {
        if (t < o) sh[t] += sh[t + o];
        __syncthreads();
    }
    if (t == 0) out[OUT_ELEMS + 1] = expf(sh[0]);
}

// ---------------------------------------------------------------------------
extern "C" void kernel_launch(void* const* d_in, const int* in_sizes, int n_in,
                              void* d_out, int out_size) {
    const float* x   = (const float*)d_in[0];
    const float* emb = (const float*)d_in[1];
    float* out = (float*)d_out;

    const int SMEME = 128 * 260 * sizeof(float);   // 133120
    const int SMEMX = 256 * 132 * sizeof(float);   // 135168
    const int SMEMM = 65536 + 2 * BSTAGE;          // 212992
    const int SMEMG = 128 * 257 * sizeof(float);   // 131584
    cudaFuncSetAttribute(k_prep_e, cudaFuncAttributeMaxDynamicSharedMemorySize, SMEME);
    cudaFuncSetAttribute(k_prep_x, cudaFuncAttributeMaxDynamicSharedMemorySize, SMEMX);
    cudaFuncSetAttribute(k_mma,    cudaFuncAttributeMaxDynamicSharedMemorySize, SMEMM);
    cudaFuncSetAttribute(k_gather, cudaFuncAttributeMaxDynamicSharedMemorySize, SMEMG);

    k_prep_e <<<KCODES / 128, 256, SMEME>>>(emb);
    k_prep_x <<<TOKENS / 128, 256, SMEMX>>>(x);
    k_mma    <<<NBMMA, 256, SMEMM>>>();
    k_rescore<<<NBRES, 256>>>(emb);
    k_gather <<<TOKENS / 128, 256, SMEMG>>>(emb, out);
    k_final  <<<1, 1024>>>(out);
}